// round 8
// baseline (speedup 1.0000x reference)
#include <cuda_runtime.h>

// Problem constants (fixed by setup_inputs: b=8, N=16384, d=128, T=64)
#define BDIM    8
#define NPIX    16384
#define DDIM    128
#define TDIM    64
#define NCAT    21
#define THRESHV 230.0f
#define TSTRIDE 132     // t tile row stride: 132 % 32 == 4 -> 8 rows at stride 4 banks, conflict-free
#define XSTR    132     // x tile row stride: rows 2bq stride 264 % 32 = 8 -> conflict-free
#define PSTR    33      // partials row stride: tt + 8bq covers all 32 banks -> conflict-free

// Output packing: flattened outputs concatenated in return order, float32.
#define OFF_MASK 2752512u                      // 8*16384*21
#define OFF_NCM  (OFF_MASK + 131072u)
#define OFF_MIND (OFF_NCM  + 131072u)
#define OFF_NC   (OFF_MIND + 131072u)

#define FMA2(acc, x, t) asm("fma.rn.f32x2 %0, %1, %2, %0;" : "+l"(acc) : "l"(x), "l"(t))

static __device__ __forceinline__ void upk2(unsigned long long v, float& a, float& b) {
    asm("mov.b64 {%0,%1}, %2;" : "=f"(a), "=f"(b) : "l"(v));
}
static __device__ __forceinline__ void cpasync16(void* smem_dst, const void* gsrc) {
    unsigned d = (unsigned)__cvta_generic_to_shared(smem_dst);
    asm volatile("cp.async.cg.shared.global [%0], [%1], 16;\n" :: "r"(d), "l"(gsrc));
}

__global__ __launch_bounds__(256, 5) void nnos_kernel(
    const float* __restrict__ frame,   // [8, 16384, 128] f32
    const float* __restrict__ tmpl,    // [64, 16384, 128] f32
    const int*   __restrict__ tclass,  // [64] int32
    float*       __restrict__ out)
{
    // part[] aliases the head of t_s[] — t_s is dead once phase 2's reads finish.
    __shared__ __align__(16) float pool[TDIM * TSTRIDE];   // 33792 B  (t_s / part)
    __shared__ __align__(16) float x_s[BDIM * XSTR];       //  4224 B
    __shared__ float x2_s[BDIM];

    float* const t_s  = pool;
    float* const part = pool;            // 64*33 floats = 8448 B <= t_s size

    const int n    = blockIdx.x;
    const int tid  = threadIdx.x;
    const int w    = tid >> 5;
    const int lane = tid & 31;

    // ---- Phase 1a: stage templates via cp.async ----
    const size_t pixbase = (size_t)n * DDIM + 4 * lane;
    #pragma unroll
    for (int i = 0; i < 8; ++i) {
        const int r = i * 8 + w;
        cpasync16(t_s + r * TSTRIDE + 4 * lane,
                  tmpl + (size_t)r * (NPIX * DDIM) + pixbase);
    }
    asm volatile("cp.async.commit_group;\n");

    // ---- Phase 1b: frame row w -> smem + x2 reduction (overlaps async copies) ----
    {
        float4 v = *(const float4*)(frame + (size_t)w * (NPIX * DDIM) + pixbase);
        *(float4*)(x_s + w * XSTR + 4 * lane) = v;
        float sq = v.x * v.x + v.y * v.y + v.z * v.z + v.w * v.w;
        #pragma unroll
        for (int off = 16; off; off >>= 1)
            sq += __shfl_xor_sync(0xffffffffu, sq, off);
        if (lane == 0) x2_s[w] = sq;
    }
    asm volatile("cp.async.wait_group 0;\n");
    __syncthreads();

    // ---- Phase 2: warp w -> (t-half tg = w&1, k-quarter kq = w>>1).
    //      lane -> (tt = lane&7, bq = lane>>3):
    //      templates t = 32tg + tt + 8m (m=0..3), batches b = 2bq, 2bq+1.
    const int tg = w & 1;
    const int kq = w >> 1;
    const int tt = lane & 7;
    const int bq = lane >> 3;

    float res[8];   // partial distances [m][j], written to part[] after re-sync
    {
        const int ko = kq * 32;
        const float* tb  = t_s + (32 * tg + tt) * TSTRIDE + ko;
        const float* xr0 = x_s + (2 * bq)     * XSTR + ko;
        const float* xr1 = x_s + (2 * bq + 1) * XSTR + ko;

        unsigned long long ax[4][2] = {{0,0},{0,0},{0,0},{0,0}};
        unsigned long long t2a[4]   = {0, 0, 0, 0};

        #pragma unroll
        for (int g = 0; g < 8; ++g) {
            ulonglong2 xv0 = *(const ulonglong2*)(xr0 + g * 4);
            ulonglong2 xv1 = *(const ulonglong2*)(xr1 + g * 4);
            #pragma unroll
            for (int m = 0; m < 4; ++m) {
                ulonglong2 tv = *(const ulonglong2*)(tb + m * 8 * TSTRIDE + g * 4);
                FMA2(t2a[m],   tv.x,  tv.x); FMA2(t2a[m],   tv.y,  tv.y);
                FMA2(ax[m][0], xv0.x, tv.x); FMA2(ax[m][0], xv0.y, tv.y);
                FMA2(ax[m][1], xv1.x, tv.x); FMA2(ax[m][1], xv1.y, tv.y);
            }
        }

        // Collapse: res[m][j] = t2q - 2*xtq  (x2 added in phase 3)
        float lo, hi;
        #pragma unroll
        for (int m = 0; m < 4; ++m) {
            upk2(t2a[m], lo, hi); const float t2m = lo + hi;
            upk2(ax[m][0], lo, hi); res[m * 2 + 0] = fmaf(-2.0f, lo + hi, t2m);
            upk2(ax[m][1], lo, hi); res[m * 2 + 1] = fmaf(-2.0f, lo + hi, t2m);
        }
    }
    __syncthreads();   // all t_s reads complete -> safe to overwrite with part[]

    // part[t*PSTR + 4*b + kq]; banks = tt + 8*bq + c -> all 32 distinct, conflict-free
    {
        float* pr = part + (32 * tg + tt) * PSTR + 8 * bq + kq;   // + m*8*PSTR + 4j
        #pragma unroll
        for (int m = 0; m < 4; ++m) {
            pr[m * 8 * PSTR + 0] = res[m * 2 + 0];
            pr[m * 8 * PSTR + 4] = res[m * 2 + 1];
        }
    }
    __syncthreads();

    // ---- Phase 3: warp w owns batch b = w; lanes scan t = lane, lane+32;
    //      butterfly argmin; fused epilogue ----
    {
        const int b = w;
        const float* p0 = part + lane * PSTR + 4 * b;
        const float* p1 = part + (lane + 32) * PSTR + 4 * b;

        float d  = (p0[0] + p0[1]) + (p0[2] + p0[3]);
        float d1 = (p1[0] + p1[1]) + (p1[2] + p1[3]);
        int  idx = lane;
        if (d1 < d) { d = d1; idx = lane + 32; }          // tie -> lower idx kept

        #pragma unroll
        for (int off = 16; off; off >>= 1) {
            float od = __shfl_xor_sync(0xffffffffu, d, off);
            int   oi = __shfl_xor_sync(0xffffffffu, idx, off);
            if (od < d || (od == d && oi < idx)) { d = od; idx = oi; }
        }
        const int   cls = tclass[idx];
        const float fd  = x2_s[b] + d;
        const int   msk = (fd <= THRESHV) ? 1 : 0;
        const size_t bn = (size_t)b * NPIX + n;

        if (lane == 0) {
            out[OFF_MASK + bn] = (float)msk;
            out[OFF_NCM  + bn] = (float)(msk ? cls : (NCAT - 1));
            out[OFF_MIND + bn] = fd;
            out[OFF_NC   + bn] = (float)cls;
        }
        if (lane < NCAT)
            out[bn * NCAT + lane] = (msk && (lane == cls)) ? 1.0f : 0.0f;
    }
}

extern "C" void kernel_launch(void* const* d_in, const int* in_sizes, int n_in,
                              void* d_out, int out_size) {
    const float* frame = (const float*)d_in[0];
    const float* tmpl  = (const float*)d_in[1];
    const int*   cls   = (const int*)d_in[2];
    float*       out   = (float*)d_out;
    (void)in_sizes; (void)n_in; (void)out_size;
    nnos_kernel<<<NPIX, 256>>>(frame, tmpl, cls, out);
}

// round 9
// speedup vs baseline: 1.0542x; 1.0542x over previous
#include <cuda_runtime.h>

// Problem constants (fixed by setup_inputs: b=8, N=16384, d=128, T=64)
#define BDIM    8
#define NPIX    16384
#define DDIM    128
#define TDIM    64
#define NCAT    21
#define THRESHV 230.0f
#define TSTRIDE 132     // t tile row stride (132 % 32 == 4)
#define XSTR    132     // x tile row stride
#define PSTR    33      // partials row stride (odd -> conflict-free scalar reads)

// Output packing: flattened outputs concatenated in return order, float32.
#define OFF_MASK 2752512u                      // 8*16384*21
#define OFF_NCM  (OFF_MASK + 131072u)
#define OFF_MIND (OFF_NCM  + 131072u)
#define OFF_NC   (OFF_MIND + 131072u)

#define FMA2(acc, x, t) asm("fma.rn.f32x2 %0, %1, %2, %0;" : "+l"(acc) : "l"(x), "l"(t))

static __device__ __forceinline__ void upk2(unsigned long long v, float& a, float& b) {
    asm("mov.b64 {%0,%1}, %2;" : "=f"(a), "=f"(b) : "l"(v));
}
static __device__ __forceinline__ void cpasync16(void* smem_dst, const void* gsrc) {
    unsigned d = (unsigned)__cvta_generic_to_shared(smem_dst);
    asm volatile("cp.async.cg.shared.global [%0], [%1], 16;\n" :: "r"(d), "l"(gsrc));
}

__global__ __launch_bounds__(256, 5) void nnos_kernel(
    const float* __restrict__ frame,   // [8, 16384, 128] f32
    const float* __restrict__ tmpl,    // [64, 16384, 128] f32
    const int*   __restrict__ tclass,  // [64] int32
    float*       __restrict__ out)
{
    // part[] aliases the head of t_s[] — t_s is dead once phase 2's reads finish
    // (guaranteed by the __syncthreads() before the partial stores).
    __shared__ __align__(16) float pool[TDIM * TSTRIDE];   // 33792 B  (t_s / part)
    __shared__ __align__(16) float x_s[BDIM * XSTR];       //  4224 B
    __shared__ float x2p[4][BDIM];                         // per-kq x2 quarter sums

    float* const t_s  = pool;
    float* const part = pool;            // 64*33 floats = 8448 B <= t_s size

    const int n    = blockIdx.x;
    const int tid  = threadIdx.x;
    const int w    = tid >> 5;
    const int lane = tid & 31;
    const int tg   = w & 1;              // t-half: templates 32tg .. 32tg+31
    const int kq   = w >> 1;             // k-quarter: columns kq*32 .. +32

    // ---- Fill: each warp cp.asyncs EXACTLY its own (t-half x k-quarter) region.
    //      lane -> (row-in-group jr = lane>>3, 16B chunk cc = lane&7):
    //      each LDGSTS covers 4 rows' contiguous 128B chunks (nL=4).
    {
        const int jr = lane >> 3;
        const int cc = lane & 7;
        const int co = kq * 32 + cc * 4;                   // column offset (floats)
        const size_t gcol = (size_t)n * DDIM + co;
        #pragma unroll
        for (int i = 0; i < 8; ++i) {                      // 32 t rows
            const int r = 32 * tg + 4 * i + jr;
            cpasync16(t_s + r * TSTRIDE + co,
                      tmpl + (size_t)r * (NPIX * DDIM) + gcol);
        }
        #pragma unroll
        for (int i = 0; i < 2; ++i) {                      // 8 x rows (dup by tg pair)
            const int b = 4 * i + jr;
            cpasync16(x_s + b * XSTR + co,
                      frame + (size_t)b * (NPIX * DDIM) + gcol);
        }
        asm volatile("cp.async.commit_group;\n");
        asm volatile("cp.async.wait_group 0;\n");
        __syncwarp();    // cross-lane visibility of this warp's own copies
    }

    // ---- x2 quarter sums: lane -> (batch bb = lane>>2, portion p = lane&3) ----
    {
        const int bb = lane >> 2;
        const int p  = lane & 3;
        const float* xq = x_s + bb * XSTR + kq * 32 + p * 8;
        float4 u = *(const float4*)(xq);
        float4 v = *(const float4*)(xq + 4);
        float sq = u.x*u.x + u.y*u.y + u.z*u.z + u.w*u.w
                 + v.x*v.x + v.y*v.y + v.z*v.z + v.w*v.w;
        sq += __shfl_xor_sync(0xffffffffu, sq, 1);
        sq += __shfl_xor_sync(0xffffffffu, sq, 2);
        if (p == 0 && tg == 0) x2p[kq][bb] = sq;
    }

    // ---- Phase 2 (R7 tiling): lane -> templates {32tg + tt, +16}, batches 4bh..4bh+3
    const int tt = lane & 15;
    const int bh = lane >> 4;
    float res[BDIM];   // 8 partial distances (t0 x4, t1 x4), stored after re-sync
    {
        const int t0 = 32 * tg + tt;
        const int ko = kq * 32;

        const float* tr0 = t_s + t0 * TSTRIDE + ko;
        const float* tr1 = t_s + (t0 + 16) * TSTRIDE + ko;
        const float* xr  = x_s + (4 * bh) * XSTR + ko;

        unsigned long long a0[4] = {0, 0, 0, 0};
        unsigned long long a1[4] = {0, 0, 0, 0};
        unsigned long long t2a0 = 0, t2a1 = 0;

        #pragma unroll
        for (int g = 0; g < 8; ++g) {
            ulonglong2 tv0 = *(const ulonglong2*)(tr0 + g * 4);
            ulonglong2 tv1 = *(const ulonglong2*)(tr1 + g * 4);
            FMA2(t2a0, tv0.x, tv0.x); FMA2(t2a0, tv0.y, tv0.y);
            FMA2(t2a1, tv1.x, tv1.x); FMA2(t2a1, tv1.y, tv1.y);
            #pragma unroll
            for (int j = 0; j < 4; ++j) {
                ulonglong2 xv = *(const ulonglong2*)(xr + j * XSTR + g * 4);
                FMA2(a0[j], xv.x, tv0.x); FMA2(a0[j], xv.y, tv0.y);
                FMA2(a1[j], xv.x, tv1.x); FMA2(a1[j], xv.y, tv1.y);
            }
        }

        // Collapse to partial distances: res = t2q - 2*xtq (x2 added in phase 3)
        float lo, hi;
        upk2(t2a0, lo, hi); const float t20 = lo + hi;
        upk2(t2a1, lo, hi); const float t21 = lo + hi;
        #pragma unroll
        for (int j = 0; j < 4; ++j) {
            upk2(a0[j], lo, hi); res[j]     = fmaf(-2.0f, lo + hi, t20);
            upk2(a1[j], lo, hi); res[4 + j] = fmaf(-2.0f, lo + hi, t21);
        }
    }
    __syncthreads();   // ALL warps done reading t_s -> safe to overwrite with part[]
                       // (also publishes x2p for phase 3)
    {
        const int t0 = 32 * tg + tt;
        float* pr = part + (8 * kq + 4 * bh);
        #pragma unroll
        for (int j = 0; j < 4; ++j) {
            pr[t0 * PSTR + j]        = res[j];
            pr[(t0 + 16) * PSTR + j] = res[4 + j];
        }
    }
    __syncthreads();

    // ---- Phase 3: warp w owns batch b = w; lanes scan t = lane, lane+32;
    //      butterfly argmin; fused epilogue ----
    {
        const int b = w;
        const float* p0 = part + lane * PSTR + b;
        const float* p1 = part + (lane + 32) * PSTR + b;

        float d  = (p0[0] + p0[8]) + (p0[16] + p0[24]);
        float d1 = (p1[0] + p1[8]) + (p1[16] + p1[24]);
        int  idx = lane;
        if (d1 < d) { d = d1; idx = lane + 32; }          // tie -> lower idx kept

        #pragma unroll
        for (int off = 16; off; off >>= 1) {
            float od = __shfl_xor_sync(0xffffffffu, d, off);
            int   oi = __shfl_xor_sync(0xffffffffu, idx, off);
            if (od < d || (od == d && oi < idx)) { d = od; idx = oi; }
        }
        const int   cls = tclass[idx];
        const float x2  = (x2p[0][b] + x2p[1][b]) + (x2p[2][b] + x2p[3][b]);
        const float fd  = x2 + d;
        const int   msk = (fd <= THRESHV) ? 1 : 0;
        const size_t bn = (size_t)b * NPIX + n;

        if (lane == 0) {
            out[OFF_MASK + bn] = (float)msk;
            out[OFF_NCM  + bn] = (float)(msk ? cls : (NCAT - 1));
            out[OFF_MIND + bn] = fd;
            out[OFF_NC   + bn] = (float)cls;
        }
        if (lane < NCAT)
            out[bn * NCAT + lane] = (msk && (lane == cls)) ? 1.0f : 0.0f;
    }
}

extern "C" void kernel_launch(void* const* d_in, const int* in_sizes, int n_in,
                              void* d_out, int out_size) {
    const float* frame = (const float*)d_in[0];
    const float* tmpl  = (const float*)d_in[1];
    const int*   cls   = (const int*)d_in[2];
    float*       out   = (float*)d_out;
    (void)in_sizes; (void)n_in; (void)out_size;
    nnos_kernel<<<NPIX, 256>>>(frame, tmpl, cls, out);
}

// round 10
// speedup vs baseline: 1.1650x; 1.1051x over previous
#include <cuda_runtime.h>
#include <cuda.h>

// Problem constants (fixed by setup_inputs: b=8, N=16384, d=128, T=64)
#define BDIM    8
#define NPIX    16384
#define DDIM    128
#define TDIM    64
#define NCAT    21
#define THRESHV 230.0f
#define TSTRIDE 132     // fallback t tile row stride
#define XSTR    132     // fallback x tile row stride
#define PSTR    33      // partials row stride (odd -> conflict-free scalar reads)

// Output packing: flattened outputs concatenated in return order, float32.
#define OFF_MASK 2752512u                      // 8*16384*21
#define OFF_NCM  (OFF_MASK + 131072u)
#define OFF_MIND (OFF_NCM  + 131072u)
#define OFF_NC   (OFF_MIND + 131072u)

#define FMA2(acc, x, t) asm("fma.rn.f32x2 %0, %1, %2, %0;" : "+l"(acc) : "l"(x), "l"(t))

static __device__ __forceinline__ void upk2(unsigned long long v, float& a, float& b) {
    asm("mov.b64 {%0,%1}, %2;" : "=f"(a), "=f"(b) : "l"(v));
}
static __device__ __forceinline__ void cpasync16(void* smem_dst, const void* gsrc) {
    unsigned d = (unsigned)__cvta_generic_to_shared(smem_dst);
    asm volatile("cp.async.cg.shared.global [%0], [%1], 16;\n" :: "r"(d), "l"(gsrc));
}

// ============================================================================
// TMA kernel: templates+frame staged by UTMALDG (no LDGSTS L1 wavefronts).
// T layout: SW128 rows r = t + 64*kc (swizzle mask = t&7). X layout: dense
// rows r = b + 8*kc. part[] aliases T after phase-2 reads complete.
// ============================================================================
__global__ __launch_bounds__(256, 5) void nnos_tma(
    const __grid_constant__ CUtensorMap mapT,
    const __grid_constant__ CUtensorMap mapX,
    const int*   __restrict__ tclass,
    float*       __restrict__ out)
{
    __shared__ __align__(1024) float T_s[8192];   // 32768 B (part alias)
    __shared__ __align__(128)  float X_s[1024];   //  4096 B
    __shared__ unsigned long long mbar_s;
    __shared__ float x2_s[BDIM];

    float* const part = T_s;                      // 64*33 floats = 8448 B

    const int n    = blockIdx.x;
    const int tid  = threadIdx.x;
    const int w    = tid >> 5;
    const int lane = tid & 31;

    const unsigned mb = (unsigned)__cvta_generic_to_shared(&mbar_s);

    if (tid == 0)
        asm volatile("mbarrier.init.shared.b64 [%0], 1;" :: "r"(mb) : "memory");
    __syncthreads();
    if (tid == 0) {
        const unsigned dT = (unsigned)__cvta_generic_to_shared(T_s);
        const unsigned dX = (unsigned)__cvta_generic_to_shared(X_s);
        asm volatile("mbarrier.arrive.expect_tx.shared.b64 _, [%0], %1;"
                     :: "r"(mb), "r"(36864u) : "memory");
        asm volatile(
            "cp.async.bulk.tensor.4d.shared::cta.global.tile.mbarrier::complete_tx::bytes "
            "[%0], [%1, {%2, %3, %4, %5}], [%6];"
            :: "r"(dT), "l"(&mapT), "r"(0), "r"(0), "r"(0), "r"(n), "r"(mb) : "memory");
        asm volatile(
            "cp.async.bulk.tensor.4d.shared::cta.global.tile.mbarrier::complete_tx::bytes "
            "[%0], [%1, {%2, %3, %4, %5}], [%6];"
            :: "r"(dX), "l"(&mapX), "r"(0), "r"(0), "r"(0), "r"(n), "r"(mb) : "memory");
    }
    // every thread waits for both bulk loads (phase parity 0)
    asm volatile(
        "{\n\t.reg .pred P;\n"
        "LW%=:\n\tmbarrier.try_wait.parity.acquire.cta.shared::cta.b64 P, [%0], 0, 0x989680;\n"
        "\t@P bra LD%=;\n"
        "\tbra LW%=;\n"
        "LD%=:\n\t}"
        :: "r"(mb) : "memory");

    // ---- x2: warp w owns batch b = w; lane -> (kc = lane>>3, granule = lane&7) ----
    {
        const float4 v = *(const float4*)((const char*)X_s
                           + ((lane >> 3) * 8 + w) * 128 + (lane & 7) * 16);
        float sq = v.x * v.x + v.y * v.y + v.z * v.z + v.w * v.w;
        #pragma unroll
        for (int off = 16; off; off >>= 1)
            sq += __shfl_xor_sync(0xffffffffu, sq, off);
        if (lane == 0) x2_s[w] = sq;
    }

    // ---- Phase 2 (R7 tiling): warp w -> (tg = w&1, kq = w>>1);
    //      lane -> templates {32tg + tt, +16}, batches 4bh .. 4bh+3 ----
    const int tg = w & 1;
    const int kq = w >> 1;
    const int tt = lane & 15;
    const int bh = lane >> 4;
    const int t0 = 32 * tg + tt;

    float res[BDIM];
    {
        const char* tb = (const char*)T_s + (kq * 64 + t0) * 128;   // row t0|kq
        const char* xb = (const char*)X_s + (kq * 8 + 4 * bh) * 128;
        const unsigned m16 = (unsigned)((tt & 7) << 4);             // SW128 mask

        unsigned long long a0[4] = {0, 0, 0, 0};
        unsigned long long a1[4] = {0, 0, 0, 0};
        unsigned long long t2a0 = 0, t2a1 = 0;

        #pragma unroll
        for (int g = 0; g < 8; ++g) {
            const unsigned off = (unsigned)(g << 4) ^ m16;
            ulonglong2 tv0 = *(const ulonglong2*)(tb + off);
            ulonglong2 tv1 = *(const ulonglong2*)(tb + 2048 + off);  // t0+16, same mask
            FMA2(t2a0, tv0.x, tv0.x); FMA2(t2a0, tv0.y, tv0.y);
            FMA2(t2a1, tv1.x, tv1.x); FMA2(t2a1, tv1.y, tv1.y);
            #pragma unroll
            for (int j = 0; j < 4; ++j) {
                ulonglong2 xv = *(const ulonglong2*)(xb + j * 128 + g * 16);
                FMA2(a0[j], xv.x, tv0.x); FMA2(a0[j], xv.y, tv0.y);
                FMA2(a1[j], xv.x, tv1.x); FMA2(a1[j], xv.y, tv1.y);
            }
        }

        float lo, hi;
        upk2(t2a0, lo, hi); const float t20 = lo + hi;
        upk2(t2a1, lo, hi); const float t21 = lo + hi;
        #pragma unroll
        for (int j = 0; j < 4; ++j) {
            upk2(a0[j], lo, hi); res[j]     = fmaf(-2.0f, lo + hi, t20);
            upk2(a1[j], lo, hi); res[4 + j] = fmaf(-2.0f, lo + hi, t21);
        }
    }
    __syncthreads();   // all T_s reads complete -> safe to overwrite with part[]
    {
        float* pr = part + (8 * kq + 4 * bh);
        #pragma unroll
        for (int j = 0; j < 4; ++j) {
            pr[t0 * PSTR + j]        = res[j];
            pr[(t0 + 16) * PSTR + j] = res[4 + j];
        }
    }
    __syncthreads();

    // ---- Phase 3: warp w owns batch b = w; butterfly argmin; fused epilogue ----
    {
        const int b = w;
        const float* p0 = part + lane * PSTR + b;
        const float* p1 = part + (lane + 32) * PSTR + b;

        float d  = (p0[0] + p0[8]) + (p0[16] + p0[24]);
        float d1 = (p1[0] + p1[8]) + (p1[16] + p1[24]);
        int  idx = lane;
        if (d1 < d) { d = d1; idx = lane + 32; }          // tie -> lower idx kept

        #pragma unroll
        for (int off = 16; off; off >>= 1) {
            float od = __shfl_xor_sync(0xffffffffu, d, off);
            int   oi = __shfl_xor_sync(0xffffffffu, idx, off);
            if (od < d || (od == d && oi < idx)) { d = od; idx = oi; }
        }
        const int   cls = tclass[idx];
        const float fd  = x2_s[b] + d;
        const int   msk = (fd <= THRESHV) ? 1 : 0;
        const size_t bn = (size_t)b * NPIX + n;

        if (lane == 0) {
            out[OFF_MASK + bn] = (float)msk;
            out[OFF_NCM  + bn] = (float)(msk ? cls : (NCAT - 1));
            out[OFF_MIND + bn] = fd;
            out[OFF_NC   + bn] = (float)cls;
        }
        if (lane < NCAT)
            out[bn * NCAT + lane] = (msk && (lane == cls)) ? 1.0f : 0.0f;
    }
}

// ============================================================================
// Fallback: Round-7 kernel verbatim (cp.async staging). Used if tensor-map
// encode is unavailable or rejects the stride layout.
// ============================================================================
__global__ __launch_bounds__(256, 5) void nnos_fallback(
    const float* __restrict__ frame,
    const float* __restrict__ tmpl,
    const int*   __restrict__ tclass,
    float*       __restrict__ out)
{
    __shared__ __align__(16) float pool[TDIM * TSTRIDE];
    __shared__ __align__(16) float x_s[BDIM * XSTR];
    __shared__ float x2_s[BDIM];

    float* const t_s  = pool;
    float* const part = pool;

    const int n    = blockIdx.x;
    const int tid  = threadIdx.x;
    const int w    = tid >> 5;
    const int lane = tid & 31;

    const size_t pixbase = (size_t)n * DDIM + 4 * lane;
    #pragma unroll
    for (int i = 0; i < 8; ++i) {
        const int r = i * 8 + w;
        cpasync16(t_s + r * TSTRIDE + 4 * lane,
                  tmpl + (size_t)r * (NPIX * DDIM) + pixbase);
    }
    asm volatile("cp.async.commit_group;\n");
    {
        float4 v = *(const float4*)(frame + (size_t)w * (NPIX * DDIM) + pixbase);
        *(float4*)(x_s + w * XSTR + 4 * lane) = v;
        float sq = v.x * v.x + v.y * v.y + v.z * v.z + v.w * v.w;
        #pragma unroll
        for (int off = 16; off; off >>= 1)
            sq += __shfl_xor_sync(0xffffffffu, sq, off);
        if (lane == 0) x2_s[w] = sq;
    }
    asm volatile("cp.async.wait_group 0;\n");
    __syncthreads();

    float res[BDIM];
    const int tg = w & 1, kq = w >> 1, tt = lane & 15, bh = lane >> 4;
    const int t0 = 32 * tg + tt;
    {
        const int ko = kq * 32;
        const float* tr0 = t_s + t0 * TSTRIDE + ko;
        const float* tr1 = t_s + (t0 + 16) * TSTRIDE + ko;
        const float* xr  = x_s + (4 * bh) * XSTR + ko;

        unsigned long long a0[4] = {0, 0, 0, 0};
        unsigned long long a1[4] = {0, 0, 0, 0};
        unsigned long long t2a0 = 0, t2a1 = 0;

        #pragma unroll
        for (int g = 0; g < 8; ++g) {
            ulonglong2 tv0 = *(const ulonglong2*)(tr0 + g * 4);
            ulonglong2 tv1 = *(const ulonglong2*)(tr1 + g * 4);
            FMA2(t2a0, tv0.x, tv0.x); FMA2(t2a0, tv0.y, tv0.y);
            FMA2(t2a1, tv1.x, tv1.x); FMA2(t2a1, tv1.y, tv1.y);
            #pragma unroll
            for (int j = 0; j < 4; ++j) {
                ulonglong2 xv = *(const ulonglong2*)(xr + j * XSTR + g * 4);
                FMA2(a0[j], xv.x, tv0.x); FMA2(a0[j], xv.y, tv0.y);
                FMA2(a1[j], xv.x, tv1.x); FMA2(a1[j], xv.y, tv1.y);
            }
        }
        float lo, hi;
        upk2(t2a0, lo, hi); const float t20 = lo + hi;
        upk2(t2a1, lo, hi); const float t21 = lo + hi;
        #pragma unroll
        for (int j = 0; j < 4; ++j) {
            upk2(a0[j], lo, hi); res[j]     = fmaf(-2.0f, lo + hi, t20);
            upk2(a1[j], lo, hi); res[4 + j] = fmaf(-2.0f, lo + hi, t21);
        }
    }
    __syncthreads();
    {
        float* pr = part + (8 * kq + 4 * bh);
        #pragma unroll
        for (int j = 0; j < 4; ++j) {
            pr[t0 * PSTR + j]        = res[j];
            pr[(t0 + 16) * PSTR + j] = res[4 + j];
        }
    }
    __syncthreads();
    {
        const int b = w;
        const float* p0 = part + lane * PSTR + b;
        const float* p1 = part + (lane + 32) * PSTR + b;

        float d  = (p0[0] + p0[8]) + (p0[16] + p0[24]);
        float d1 = (p1[0] + p1[8]) + (p1[16] + p1[24]);
        int  idx = lane;
        if (d1 < d) { d = d1; idx = lane + 32; }

        #pragma unroll
        for (int off = 16; off; off >>= 1) {
            float od = __shfl_xor_sync(0xffffffffu, d, off);
            int   oi = __shfl_xor_sync(0xffffffffu, idx, off);
            if (od < d || (od == d && oi < idx)) { d = od; idx = oi; }
        }
        const int   cls = tclass[idx];
        const float fd  = x2_s[b] + d;
        const int   msk = (fd <= THRESHV) ? 1 : 0;
        const size_t bn = (size_t)b * NPIX + n;

        if (lane == 0) {
            out[OFF_MASK + bn] = (float)msk;
            out[OFF_NCM  + bn] = (float)(msk ? cls : (NCAT - 1));
            out[OFF_MIND + bn] = fd;
            out[OFF_NC   + bn] = (float)cls;
        }
        if (lane < NCAT)
            out[bn * NCAT + lane] = (msk && (lane == cls)) ? 1.0f : 0.0f;
    }
}

// ============================================================================
// Host launcher: build tensor maps via driver entry point (no -lcuda link);
// fall back to the R7 kernel if anything is rejected.
// ============================================================================
typedef CUresult (*PFN_TMEncode)(
    CUtensorMap*, CUtensorMapDataType, cuuint32_t, void*,
    const cuuint64_t*, const cuuint64_t*, const cuuint32_t*, const cuuint32_t*,
    CUtensorMapInterleave, CUtensorMapSwizzle, CUtensorMapL2promotion,
    CUtensorMapFloatOOBfill);

extern "C" void kernel_launch(void* const* d_in, const int* in_sizes, int n_in,
                              void* d_out, int out_size) {
    const float* frame = (const float*)d_in[0];
    const float* tmpl  = (const float*)d_in[1];
    const int*   cls   = (const int*)d_in[2];
    float*       out   = (float*)d_out;
    (void)in_sizes; (void)n_in; (void)out_size;

    static PFN_TMEncode enc = nullptr;
    static bool looked_up = false;
    if (!looked_up) {
        looked_up = true;
        void* p = nullptr;
        cudaDriverEntryPointQueryResult qr;
        if (cudaGetDriverEntryPoint("cuTensorMapEncodeTiled", &p,
                                    cudaEnableDefault, &qr) == cudaSuccess &&
            qr == cudaDriverEntryPointSuccess)
            enc = (PFN_TMEncode)p;
    }

    bool use_tma = false;
    CUtensorMap mT, mX;
    if (enc) {
        // templates: (ki=32)(t=64)(kc=4)(n=16384); elem offset =
        //   t*8388608B + kc*128B + n*512B + ki*4B
        cuuint64_t dT[4] = {32, 64, 4, 16384};
        cuuint64_t sT[3] = {8388608ULL, 128ULL, 512ULL};
        cuuint32_t bT[4] = {32, 64, 4, 1};
        cuuint32_t eS[4] = {1, 1, 1, 1};
        CUresult r1 = enc(&mT, CU_TENSOR_MAP_DATA_TYPE_FLOAT32, 4, (void*)tmpl,
                          dT, sT, bT, eS,
                          CU_TENSOR_MAP_INTERLEAVE_NONE,
                          CU_TENSOR_MAP_SWIZZLE_128B,
                          CU_TENSOR_MAP_L2_PROMOTION_L2_128B,
                          CU_TENSOR_MAP_FLOAT_OOB_FILL_NONE);
        // frame: (ki=32)(b=8)(kc=4)(n=16384), dense rows (no swizzle)
        cuuint64_t dX[4] = {32, 8, 4, 16384};
        cuuint64_t sX[3] = {8388608ULL, 128ULL, 512ULL};
        cuuint32_t bX[4] = {32, 8, 4, 1};
        CUresult r2 = enc(&mX, CU_TENSOR_MAP_DATA_TYPE_FLOAT32, 4, (void*)frame,
                          dX, sX, bX, eS,
                          CU_TENSOR_MAP_INTERLEAVE_NONE,
                          CU_TENSOR_MAP_SWIZZLE_NONE,
                          CU_TENSOR_MAP_L2_PROMOTION_L2_128B,
                          CU_TENSOR_MAP_FLOAT_OOB_FILL_NONE);
        use_tma = (r1 == CUDA_SUCCESS && r2 == CUDA_SUCCESS);
    }

    if (use_tma)
        nnos_tma<<<NPIX, 256>>>(mT, mX, cls, out);
    else
        nnos_fallback<<<NPIX, 256>>>(frame, tmpl, cls, out);
}